// round 2
// baseline (speedup 1.0000x reference)
#include <cuda_runtime.h>
#include <math.h>

// Fixed problem shapes
#define Bb 16
#define Mm 1024
#define Ww 256
#define Hh 8
#define NWn 2
#define NRn 4

// Small scratch (allocation-free rule: __device__ globals)
static __device__ float g_keynorm[Bb * Hh];
static __device__ float g_splus[Bb * Hh];
static __device__ float g_rwsum[Bb * NRn];

// ---------------------------------------------------------------------------
// Pre-pass: per (b,h) key L2 norms + softplus(strength); per (b,n) sum_m rw.
// One warp per task.
// ---------------------------------------------------------------------------
__global__ void pre_kernel(const float* __restrict__ keys,
                           const float* __restrict__ strengths,
                           const float* __restrict__ rw) {
    int blk = blockIdx.x;
    int lane = threadIdx.x;
    if (blk < Bb * Hh) {
        const float* kp = keys + (size_t)blk * Ww;
        float s = 0.f;
        #pragma unroll
        for (int i = lane; i < Ww; i += 32) { float v = kp[i]; s += v * v; }
        #pragma unroll
        for (int o = 16; o; o >>= 1) s += __shfl_xor_sync(0xffffffffu, s, o);
        if (lane == 0) {
            g_keynorm[blk] = sqrtf(s + 1e-6f);
            float x = strengths[blk];
            g_splus[blk] = (x > 20.f) ? x : log1pf(expf(x));
        }
    } else {
        int idx = blk - Bb * Hh;            // (b,n)
        const float* rp = rw + (size_t)idx * Mm;
        float s = 0.f;
        for (int i = lane; i < Mm; i += 32) s += rp[i];
        #pragma unroll
        for (int o = 16; o; o >>= 1) s += __shfl_xor_sync(0xffffffffu, s, o);
        if (lane == 0) g_rwsum[idx] = s;
    }
}

// ---------------------------------------------------------------------------
// Fused main kernel: one warp per (b, m) row.
//  - erase/write update of memory row -> out_mem
//  - 8 key dot products + row norm   -> sharp scores into out_cos
//  - usage update                    -> out_usage
// Block = 8 warps = 8 consecutive rows of one batch; keys/ev/wv in shared.
// ---------------------------------------------------------------------------
__global__ void __launch_bounds__(256) main_kernel(
    const float* __restrict__ memory,
    const float* __restrict__ keys,
    const float* __restrict__ ww,
    const float* __restrict__ fg,
    const float* __restrict__ rw,
    const float* __restrict__ pu,
    const float* __restrict__ ev,
    const float* __restrict__ wv,
    float* __restrict__ out_mem,
    float* __restrict__ out_cos,
    float* __restrict__ out_usage)
{
    __shared__ float keys_sh[Hh * Ww];   // 8 KB
    __shared__ float ev_sh[NWn * Ww];    // 2 KB
    __shared__ float wv_sh[NWn * Ww];    // 2 KB

    int b  = blockIdx.x >> 7;            // 128 blocks per batch
    int m0 = (blockIdx.x & 127) * 8;
    int tid = threadIdx.x;

    for (int i = tid; i < Hh * Ww; i += 256) keys_sh[i] = keys[(size_t)b * Hh * Ww + i];
    for (int i = tid; i < NWn * Ww; i += 256) {
        ev_sh[i] = ev[(size_t)b * NWn * Ww + i];
        wv_sh[i] = wv[(size_t)b * NWn * Ww + i];
    }
    __syncthreads();

    int warp = tid >> 5, lane = tid & 31;
    int m = m0 + warp;

    const float4* mrow = (const float4*)(memory  + (size_t)(b * Mm + m) * Ww);
    float4*       orow = (float4*)      (out_mem + (size_t)(b * Mm + m) * Ww);
    const float4* k4   = (const float4*)keys_sh;
    const float4* e4p  = (const float4*)ev_sh;
    const float4* v4p  = (const float4*)wv_sh;

    float w0 = ww[(size_t)(b * NWn + 0) * Mm + m];
    float w1 = ww[(size_t)(b * NWn + 1) * Mm + m];

    float norm2 = 0.f;
    float dot[Hh];
    #pragma unroll
    for (int h = 0; h < Hh; h++) dot[h] = 0.f;

    #pragma unroll
    for (int j = 0; j < 2; j++) {
        int i4 = lane + j * 32;          // float4 index within row (64 total)
        float4 mv = mrow[i4];
        float4 e0 = e4p[i4],      e1 = e4p[64 + i4];
        float4 v0 = v4p[i4],      v1 = v4p[64 + i4];

        float4 o;
        float ex = fminf(fmaxf(w0 * e0.x + w1 * e1.x, 0.f), 1.f);
        float ey = fminf(fmaxf(w0 * e0.y + w1 * e1.y, 0.f), 1.f);
        float ez = fminf(fmaxf(w0 * e0.z + w1 * e1.z, 0.f), 1.f);
        float ew = fminf(fmaxf(w0 * e0.w + w1 * e1.w, 0.f), 1.f);
        o.x = mv.x * (1.f - ex) + w0 * v0.x + w1 * v1.x;
        o.y = mv.y * (1.f - ey) + w0 * v0.y + w1 * v1.y;
        o.z = mv.z * (1.f - ez) + w0 * v0.z + w1 * v1.z;
        o.w = mv.w * (1.f - ew) + w0 * v0.w + w1 * v1.w;
        orow[i4] = o;

        norm2 += mv.x * mv.x + mv.y * mv.y + mv.z * mv.z + mv.w * mv.w;

        #pragma unroll
        for (int h = 0; h < Hh; h++) {
            float4 kv = k4[h * 64 + i4];
            dot[h] += kv.x * mv.x + kv.y * mv.y + kv.z * mv.z + kv.w * mv.w;
        }
    }

    // Butterfly reduce: every lane ends with the full sums
    #pragma unroll
    for (int o = 16; o; o >>= 1) {
        norm2 += __shfl_xor_sync(0xffffffffu, norm2, o);
        #pragma unroll
        for (int h = 0; h < Hh; h++)
            dot[h] += __shfl_xor_sync(0xffffffffu, dot[h], o);
    }

    float mn = sqrtf(norm2 + 1e-6f);

    if (lane < Hh) {
        // avoid dynamic register indexing: predicated select
        float myd = 0.f;
        #pragma unroll
        for (int h = 0; h < Hh; h++) if (lane == h) myd = dot[h];
        int bh = b * Hh + lane;
        float sharp = myd / (mn * g_keynorm[bh] + 1e-6f) * g_splus[bh];
        out_cos[(size_t)bh * Mm + m] = sharp;
    }

    if (lane == 8) {
        float u = pu[(size_t)b * Mm + m] + w0 + w1;
        #pragma unroll
        for (int n = 0; n < NRn; n++)
            u -= rw[(size_t)(b * NRn + n) * Mm + m] * fg[b * NRn + n];
        out_usage[(size_t)b * Mm + m] = fminf(fmaxf(u, 0.f), 1.f);
    }
}

// ---------------------------------------------------------------------------
// In-place softmax over M=1024 per (b,h) row.
// ---------------------------------------------------------------------------
__global__ void __launch_bounds__(256) softmax_kernel(float* __restrict__ cosr) {
    __shared__ float red[8];
    float* p = cosr + (size_t)blockIdx.x * Mm;
    int tid = threadIdx.x;

    float v[4];
    float mx = -INFINITY;
    #pragma unroll
    for (int j = 0; j < 4; j++) { v[j] = p[tid + j * 256]; mx = fmaxf(mx, v[j]); }
    #pragma unroll
    for (int o = 16; o; o >>= 1) mx = fmaxf(mx, __shfl_xor_sync(0xffffffffu, mx, o));
    if ((tid & 31) == 0) red[tid >> 5] = mx;
    __syncthreads();
    float bm = red[0];
    #pragma unroll
    for (int i = 1; i < 8; i++) bm = fmaxf(bm, red[i]);
    __syncthreads();

    float s = 0.f;
    #pragma unroll
    for (int j = 0; j < 4; j++) { v[j] = expf(v[j] - bm); s += v[j]; }
    #pragma unroll
    for (int o = 16; o; o >>= 1) s += __shfl_xor_sync(0xffffffffu, s, o);
    if ((tid & 31) == 0) red[tid >> 5] = s;
    __syncthreads();
    float bs = 0.f;
    #pragma unroll
    for (int i = 0; i < 8; i++) bs += red[i];
    float inv = 1.f / bs;
    #pragma unroll
    for (int j = 0; j < 4; j++) p[tid + j * 256] = v[j] * inv;
}

// ---------------------------------------------------------------------------
// read_output[b,w] = sum_n (sum_m rw[b,n,m]) * rv[b,n,w]
// ---------------------------------------------------------------------------
__global__ void readout_kernel(const float* __restrict__ rv, float* __restrict__ outr) {
    int b = blockIdx.x, w = threadIdx.x;
    float s = 0.f;
    #pragma unroll
    for (int n = 0; n < NRn; n++)
        s += g_rwsum[b * NRn + n] * rv[(size_t)(b * NRn + n) * Ww + w];
    outr[(size_t)b * Ww + w] = s;
}

// ---------------------------------------------------------------------------
extern "C" void kernel_launch(void* const* d_in, const int* in_sizes, int n_in,
                              void* d_out, int out_size) {
    const float* memory    = (const float*)d_in[0];
    const float* keys      = (const float*)d_in[1];
    const float* strengths = (const float*)d_in[2];
    const float* ww        = (const float*)d_in[3];
    const float* fg        = (const float*)d_in[4];
    const float* rw        = (const float*)d_in[5];
    const float* prev_link = (const float*)d_in[6];
    // d_in[7] = prev_precedence_weights (unused: output precedence := write_weights)
    const float* pu        = (const float*)d_in[8];
    const float* ev        = (const float*)d_in[9];
    const float* wv        = (const float*)d_in[10];
    const float* rv        = (const float*)d_in[11];
    float* out = (float*)d_out;

    const size_t N_MEM  = (size_t)Bb * Mm * Ww;       // 4,194,304
    const size_t N_COS  = (size_t)Bb * Hh * Mm;       //   131,072
    const size_t N_LINK = (size_t)Bb * NWn * Mm * Mm; // 33,554,432
    const size_t N_PREC = (size_t)Bb * NWn * Mm;      //    32,768
    const size_t N_US   = (size_t)Bb * Mm;            //    16,384

    float* out_mem   = out;
    float* out_cos   = out + N_MEM;
    float* out_link  = out_cos + N_COS;
    float* out_prec  = out_link + N_LINK;
    float* out_usage = out_prec + N_PREC;
    float* out_read  = out_usage + N_US;

    // Big passthrough copies (dominant HBM traffic)
    cudaMemcpyAsync(out_link, prev_link, N_LINK * sizeof(float),
                    cudaMemcpyDeviceToDevice, 0);
    cudaMemcpyAsync(out_prec, ww, N_PREC * sizeof(float),
                    cudaMemcpyDeviceToDevice, 0);

    pre_kernel<<<Bb * Hh + Bb * NRn, 32>>>(keys, strengths, rw);
    main_kernel<<<(Bb * Mm) / 8, 256>>>(memory, keys, ww, fg, rw, pu, ev, wv,
                                        out_mem, out_cos, out_usage);
    softmax_kernel<<<Bb * Hh, 256>>>(out_cos);
    readout_kernel<<<Bb, Ww>>>(rv, out_read);
}